// round 17
// baseline (speedup 1.0000x reference)
#include <cuda_runtime.h>
#include <cuda_fp16.h>

// Factorized ray-marching: x@W1+b1 = p1 + alpha*u.
// R17: B-fragment register double-use. Block = 32 rows / 16 warps (512 thr);
// Phase-A warp = 32 rows x 16 cols so each B-frag load feeds TWO row-group
// MMAs (W1 L1 traffic halved: 4KB/row -> 2KB/row). Tail reads normalized r
// from smem instead of re-reading gmem. Phase B: R16's 6-node Chebyshev
// collocation + beta-Horner, 2 rows/warp.

#define D_DIM 128
#define H_DIM 256
#define KT    8
#define NT    32
#define NND   6              // Chebyshev nodes / degree-(NND-1) fit
#define UPAD  264            // halves per u row
#define RPAD  136            // halves per staged r row
#define PI_F  3.14159265358979f

__device__ __half2 g_p1h2[H_DIM / 2];
__device__ __half2 g_w2h2[H_DIM / 2];
__device__ uint2   g_Bfrag[KT * NT * 32];   // 64 KB: W1 in HMMA B-fragment layout
__device__ float   g_C[NND * NND];          // DCT matrix (with weights)
__device__ float   g_xk[NND];               // Chebyshev nodes on [-1,1]

static __device__ __forceinline__ float tanh_fast(float x) {
    float y; asm("tanh.approx.f32 %0, %1;" : "=f"(y) : "f"(x)); return y;
}
static __device__ __forceinline__ __half2 tanh2_fast(__half2 x) {
    __half2 y;
    asm("tanh.approx.f16x2 %0, %1;" : "=r"(*(unsigned*)&y) : "r"(*(unsigned*)&x));
    return y;
}
static __device__ __forceinline__ unsigned h2bits(__half2 v) { return *(unsigned*)&v; }
static __device__ __forceinline__ void mma16816(float& c0, float& c1, float& c2, float& c3,
                                                unsigned a0, unsigned a1, unsigned a2, unsigned a3,
                                                unsigned b0, unsigned b1) {
    asm volatile("mma.sync.aligned.m16n8k16.row.col.f32.f16.f16.f32 "
                 "{%0,%1,%2,%3}, {%4,%5,%6,%7}, {%8,%9}, {%0,%1,%2,%3};"
                 : "+f"(c0), "+f"(c1), "+f"(c2), "+f"(c3)
                 : "r"(a0), "r"(a1), "r"(a2), "r"(a3), "r"(b0), "r"(b1));
}

// prep (grid 9, block 1024): block 0 -> p1 + half copies + DCT consts;
// blocks 1..8 -> W1 B-fragment packing.
__global__ __launch_bounds__(1024)
void prep_kernel(const float* __restrict__ pivot,
                 const float* __restrict__ W1,
                 const float* __restrict__ b1,
                 const float* __restrict__ w2) {
    if (blockIdx.x == 0) {
        __shared__ float red[4][H_DIM];
        __shared__ float sp1[H_DIM];
        const int j  = threadIdx.x & 255;
        const int dg = threadIdx.x >> 8;
        float s = 0.f;
        const int d0 = dg * 32;
#pragma unroll 8
        for (int d = d0; d < d0 + 32; ++d)
            s = fmaf(pivot[d], W1[(size_t)d * H_DIM + j], s);
        red[dg][j] = s;
        __syncthreads();
        if (dg == 0)
            sp1[j] = red[0][j] + red[1][j] + red[2][j] + red[3][j] + b1[j];
        __syncthreads();
        if (threadIdx.x < H_DIM / 2) {
            g_p1h2[threadIdx.x] = __floats2half2_rn(sp1[2 * threadIdx.x],
                                                    sp1[2 * threadIdx.x + 1]);
            g_w2h2[threadIdx.x] = __floats2half2_rn(w2[2 * threadIdx.x],
                                                    w2[2 * threadIdx.x + 1]);
        }
        // DCT-II matrix with quadrature weights
        if (threadIdx.x >= 512 && threadIdx.x < 512 + NND * NND) {
            const int e = threadIdx.x - 512;
            const int cj = e / NND, ck = e % NND;
            const float w = (cj == 0) ? (1.f / NND) : (2.f / NND);
            g_C[e] = w * cosf((float)cj * ((float)ck + 0.5f) * (PI_F / NND));
        }
        if (threadIdx.x >= 576 && threadIdx.x < 576 + NND) {
            const int k = threadIdx.x - 576;
            g_xk[k] = cosf(((float)k + 0.5f) * (PI_F / NND));
        }
    } else {
        const int e = (blockIdx.x - 1) * 1024 + threadIdx.x;   // 0..8191
        const int tile = e >> 5;
        const int lane = e & 31;
        const int kt = tile / NT;
        const int nt = tile % NT;
        const int g = lane >> 2, t4 = lane & 3;
        const int k0 = kt * 16 + t4 * 2;
        const int col = nt * 8 + g;
        __half2 b0v = __floats2half2_rn(W1[(size_t)k0 * H_DIM + col],
                                        W1[(size_t)(k0 + 1) * H_DIM + col]);
        __half2 b1v = __floats2half2_rn(W1[(size_t)(k0 + 8) * H_DIM + col],
                                        W1[(size_t)(k0 + 9) * H_DIM + col]);
        g_Bfrag[tile * 32 + lane] = make_uint2(h2bits(b0v), h2bits(b1v));
    }
}

// ============== fused main kernel: block = 32 rows, 16 warps ==============
__global__ __launch_bounds__(512, 2)
void main_kernel(const float* __restrict__ r,
                 const float* __restrict__ s_in,
                 const float* __restrict__ pivot,
                 const float* __restrict__ b2,
                 const int* __restrict__ n_iter_ptr,
                 float* __restrict__ out,
                 int B) {
    __shared__ __half u_sh[32][UPAD];     // 16.5 KB
    __shared__ __half r_sh[32][RPAD];     // 8.5 KB (normalized r, half)
    __shared__ float  C_sh[NND * NND];
    __shared__ float  x_sh[NND];

    const int lane = threadIdx.x & 31;
    const int wib  = threadIdx.x >> 5;          // 0..15
    const int base_row = blockIdx.x * 32;

    // ---------- Stage 0: stage r (normalized half) + copy DCT consts ----------
    if (threadIdx.x < NND * NND) C_sh[threadIdx.x] = g_C[threadIdx.x];
    else if (threadIdx.x < NND * NND + NND) x_sh[threadIdx.x - NND * NND] = g_xk[threadIdx.x - NND * NND];
#pragma unroll
    for (int p = 0; p < 2; ++p) {
        const int lrow = wib + p * 16;
        const int row = base_row + lrow;
        float4 v = (row < B) ? ((const float4*)(r + (size_t)row * D_DIM))[lane]
                             : make_float4(0.f, 0.f, 0.f, 0.f);
        float ss = fmaf(v.x, v.x, fmaf(v.y, v.y, fmaf(v.z, v.z, v.w * v.w)));
#pragma unroll
        for (int o = 16; o; o >>= 1) ss += __shfl_xor_sync(0xffffffffu, ss, o);
        const float inv = rsqrtf(ss);
        *(__half2*)&r_sh[lrow][lane * 4]     = __floats2half2_rn(v.x * inv, v.y * inv);
        *(__half2*)&r_sh[lrow][lane * 4 + 2] = __floats2half2_rn(v.z * inv, v.w * inv);
    }
    __syncthreads();

    // ---------- Phase A: HMMA. warp = 32 rows x 16 cols (2 n-tiles, 2 row-grps) ----------
    {
        const int ntg = wib * 2;                   // this warp's 2 n-tiles
        const int g4 = lane >> 2, t4 = lane & 3;

        float acc[2][2][4];                        // [tile][rowgrp][quad]
#pragma unroll
        for (int t = 0; t < 2; ++t)
#pragma unroll
            for (int g = 0; g < 2; ++g)
#pragma unroll
                for (int q = 0; q < 4; ++q) acc[t][g][q] = 0.f;

#pragma unroll
        for (int kt = 0; kt < KT; ++kt) {
            const int cbase = kt * 16 + t4 * 2;
            unsigned a0[2], a1[2], a2[2], a3[2];
#pragma unroll
            for (int g = 0; g < 2; ++g) {
                const int rb = g * 16 + g4;
                a0[g] = *(const unsigned*)&r_sh[rb][cbase];
                a1[g] = *(const unsigned*)&r_sh[rb + 8][cbase];
                a2[g] = *(const unsigned*)&r_sh[rb][cbase + 8];
                a3[g] = *(const unsigned*)&r_sh[rb + 8][cbase + 8];
            }
            const uint2* bb = g_Bfrag + (size_t)(kt * NT + ntg) * 32 + lane;
            uint2 bf0 = __ldg(bb);
            uint2 bf1 = __ldg(bb + 32);
            // each B-fragment feeds BOTH row groups
#pragma unroll
            for (int g = 0; g < 2; ++g) {
                mma16816(acc[0][g][0], acc[0][g][1], acc[0][g][2], acc[0][g][3],
                         a0[g], a1[g], a2[g], a3[g], bf0.x, bf0.y);
                mma16816(acc[1][g][0], acc[1][g][1], acc[1][g][2], acc[1][g][3],
                         a0[g], a1[g], a2[g], a3[g], bf1.x, bf1.y);
            }
        }

#pragma unroll
        for (int t = 0; t < 2; ++t) {
            const int col = (ntg + t) * 8 + t4 * 2;
#pragma unroll
            for (int g = 0; g < 2; ++g) {
                const int rb = g * 16 + g4;
                *(__half2*)&u_sh[rb][col]     = __floats2half2_rn(acc[t][g][0], acc[t][g][1]);
                *(__half2*)&u_sh[rb + 8][col] = __floats2half2_rn(acc[t][g][2], acc[t][g][3]);
            }
        }
    }
    __syncthreads();

    // ---------- Phase B: 6-node Chebyshev collocation + beta-Horner ----------
    const int l16 = lane & 15;
    const int lrow = wib * 2 + (lane >> 4);     // 0..31
    const int row = base_row + lrow;
    if (row >= B) return;

    __half2 u2[8], p12[8], w22[8];
    {
        const uint4* up = (const uint4*)(&u_sh[lrow][0]) + l16 * 2;
        const uint4* pp = (const uint4*)g_p1h2 + l16 * 2;
        const uint4* wp = (const uint4*)g_w2h2 + l16 * 2;
#pragma unroll
        for (int v = 0; v < 2; ++v) {
            uint4 uu = up[v];
            uint4 aa = __ldg(pp + v), bb = __ldg(wp + v);
            u2[v * 4 + 0] = *(__half2*)&uu.x; u2[v * 4 + 1] = *(__half2*)&uu.y;
            u2[v * 4 + 2] = *(__half2*)&uu.z; u2[v * 4 + 3] = *(__half2*)&uu.w;
            p12[v * 4 + 0] = *(__half2*)&aa.x; p12[v * 4 + 1] = *(__half2*)&aa.y;
            p12[v * 4 + 2] = *(__half2*)&aa.z; p12[v * 4 + 3] = *(__half2*)&aa.w;
            w22[v * 4 + 0] = *(__half2*)&bb.x; w22[v * 4 + 1] = *(__half2*)&bb.y;
            w22[v * 4 + 2] = *(__half2*)&bb.z; w22[v * 4 + 3] = *(__half2*)&bb.w;
        }
    }

    const float b2v = b2[0];
    const int n = n_iter_ptr ? *n_iter_ptr : 20;
    const float h = (n > 0) ? 0.05f * (float)n : 1.f;   // alpha in [0, 2h]
    const float c = h;
    const float step = 0.05f / h;
    const __half2 h2z = __floats2half2_rn(0.f, 0.f);

    // evaluate f at NND Chebyshev nodes (independent)
    float yk[NND];
#pragma unroll
    for (int k = 0; k < NND; ++k) {
        const float ak = fmaf(h, x_sh[k], c);
        const __half2 a2h = __float2half2_rn(ak);
        __half2 s0 = h2z, s1 = h2z;
#pragma unroll
        for (int q = 0; q < 8; q += 2) {
            __half2 za = __hfma2(a2h, u2[q],     p12[q]);
            __half2 zb = __hfma2(a2h, u2[q + 1], p12[q + 1]);
            s0 = __hfma2(tanh2_fast(za), w22[q],     s0);
            s1 = __hfma2(tanh2_fast(zb), w22[q + 1], s1);
        }
        __half2 acc2 = __hadd2(s0, s1);
        yk[k] = __low2float(acc2) + __high2float(acc2);
    }
#pragma unroll
    for (int o = 1; o <= 8; o <<= 1) {
#pragma unroll
        for (int k = 0; k < NND; ++k)
            yk[k] += __shfl_xor_sync(0xffffffffu, yk[k], o);
    }

    // Chebyshev coefficients + monomial conversion (degree 5)
    float a[NND];
#pragma unroll
    for (int j = 0; j < NND; ++j) {
        float sj = 0.f;
#pragma unroll
        for (int k = 0; k < NND; ++k)
            sj = fmaf(C_sh[j * NND + k], yk[k], sj);
        a[j] = sj;
    }
    const float m0 = a[0] - a[2] + a[4];
    const float m1 = a[1] - 3.f * a[3] + 5.f * a[5];
    const float m2 = 2.f * a[2] - 8.f * a[4];
    const float m3 = 4.f * a[3] - 20.f * a[5];
    const float m4 = 8.f * a[4];
    const float m5 = 16.f * a[5];

    // 20-step recurrence in beta: pure per-lane Horner
    float beta = -1.f;
    for (int it = 0; it < n; ++it) {
        float f = fmaf(beta, m5, m4);
        f = fmaf(beta, f, m3);
        f = fmaf(beta, f, m2);
        f = fmaf(beta, f, m1);
        f = fmaf(beta, f, m0);
        beta += step * (1.0f + tanh_fast(f + b2v));
    }
    const float alpha = fmaf(h, beta, c);

    // ---------- tail: out = pivot + (sig*alpha) * r_norm, r_norm from smem ----------
    const float sv = s_in[row];
    const float sig = 1.0f / (1.0f + __expf(-sv));
    const float fscale = sig * alpha;            // applied to NORMALIZED r

    const uint4 rh = *(const uint4*)(&r_sh[lrow][l16 * 8]);   // 8 halves
    const __half2 rh0 = *(const __half2*)&rh.x;
    const __half2 rh1 = *(const __half2*)&rh.y;
    const __half2 rh2 = *(const __half2*)&rh.z;
    const __half2 rh3 = *(const __half2*)&rh.w;

    const float4* pv4 = (const float4*)pivot + l16 * 2;
    float4* ov4 = (float4*)(out + (size_t)row * D_DIM) + l16 * 2;
    float4 pv = pv4[0];
    float4 o;
    o.x = fmaf(fscale, __low2float(rh0),  pv.x);
    o.y = fmaf(fscale, __high2float(rh0), pv.y);
    o.z = fmaf(fscale, __low2float(rh1),  pv.z);
    o.w = fmaf(fscale, __high2float(rh1), pv.w);
    ov4[0] = o;
    pv = pv4[1];
    o.x = fmaf(fscale, __low2float(rh2),  pv.x);
    o.y = fmaf(fscale, __high2float(rh2), pv.y);
    o.z = fmaf(fscale, __low2float(rh3),  pv.z);
    o.w = fmaf(fscale, __high2float(rh3), pv.w);
    ov4[1] = o;
}

extern "C" void kernel_launch(void* const* d_in, const int* in_sizes, int n_in,
                              void* d_out, int out_size) {
    const float* r     = (const float*)d_in[0];   // [B,128]
    const float* s     = (const float*)d_in[1];   // [B,1]
    const float* pivot = (const float*)d_in[2];   // [128]
    const float* W1    = (const float*)d_in[3];   // [128,256]
    const float* b1    = (const float*)d_in[4];   // [256]
    const float* w2    = (const float*)d_in[5];   // [256]
    const float* b2    = (const float*)d_in[6];   // [1]
    const int* n_iter  = (n_in > 7) ? (const int*)d_in[7] : nullptr;
    float* out = (float*)d_out;

    const int B = in_sizes[0] / D_DIM;

    prep_kernel<<<9, 1024>>>(pivot, W1, b1, w2);

    const int blocks = (B + 31) / 32;
    main_kernel<<<blocks, 512>>>(r, s, pivot, b2, n_iter, out, B);
}